// round 8
// baseline (speedup 1.0000x reference)
#include <cuda_runtime.h>
#include <cuda_fp16.h>
#include <cstdint>

#define M_TOK 8192
#define DIN   4096
#define DOUT  4096
#define NE    8
#define RK    16
#define EQ    256
#define ER    128
#define NPROJ 640           // EQ + EQ + ER
#define INV_SQRT_DK 0.17677669529663687f

// ---------------- scratch (no allocs allowed) ----------------
__device__ __half g_xh [(size_t)M_TOK * DIN];
__device__ __half g_Wh [(size_t)DOUT  * DIN];
__device__ __half g_Wp [(size_t)NPROJ * DIN];
__device__ __half g_Bmt[(size_t)DOUT  * ER];
__device__ float  g_proj[(size_t)M_TOK * NPROJ];
__device__ __half g_gate[(size_t)M_TOK * ER];

// ---------------- PTX helpers (base-target only) ----------
__device__ __forceinline__ uint32_t cvta_s(const void* p) {
    return (uint32_t)__cvta_generic_to_shared(p);
}
__device__ __forceinline__ void cp16(uint32_t dst, const void* src) {
    asm volatile("cp.async.cg.shared.global [%0], [%1], 16;" :: "r"(dst), "l"(src));
}
#define CP_COMMIT() asm volatile("cp.async.commit_group;" ::: "memory")
#define CP_WAIT1()  asm volatile("cp.async.wait_group 1;"  ::: "memory")

__device__ __forceinline__ void ldsm4(uint32_t& r0, uint32_t& r1,
                                      uint32_t& r2, uint32_t& r3, uint32_t addr) {
    asm volatile("ldmatrix.sync.aligned.m8n8.x4.shared.b16 {%0,%1,%2,%3}, [%4];"
                 : "=r"(r0), "=r"(r1), "=r"(r2), "=r"(r3) : "r"(addr));
}
__device__ __forceinline__ void mma16816(float* d, const uint32_t* a,
                                         uint32_t b0, uint32_t b1) {
    asm volatile(
        "mma.sync.aligned.m16n8k16.row.col.f32.f16.f16.f32 "
        "{%0,%1,%2,%3}, {%4,%5,%6,%7}, {%8,%9}, {%0,%1,%2,%3};"
        : "+f"(d[0]), "+f"(d[1]), "+f"(d[2]), "+f"(d[3])
        : "r"(a[0]), "r"(a[1]), "r"(a[2]), "r"(a[3]), "r"(b0), "r"(b1));
}

// ---------------------------------------------------------------------------
// Generalized HMMA fp16 GEMM.
//   Warp grid WMW x WNW; warp tile (MF*16) x (NF*8); CTA tile BM x BN.
//   BK K-slice per stage; 3-slot, depth-2 cp.async pipeline.
//   C = A @ B^T (+ gA @ gB^T over K=ER if LORA) (+ bias).
//   A[M,K], B[N,K] row-major fp16, K contiguous.
//   Smem rows padded to BK+8 halfs -> ldmatrix conflict-free.
// ---------------------------------------------------------------------------
template<int WMW, int WNW, int MF, int NF, int BK, int MINB, bool LORA>
__global__ __launch_bounds__(WMW * WNW * 32, MINB)
void gemm_hmma(const __half* __restrict__ A, const __half* __restrict__ B,
               const __half* __restrict__ gA, const __half* __restrict__ gB,
               const float* __restrict__ bias,
               float* __restrict__ C, int ldc, int K)
{
    constexpr int THREADS = WMW * WNW * 32;
    constexpr int BM  = WMW * MF * 16;
    constexpr int BN  = WNW * NF * 8;
    constexpr int WN  = NF * 8;
    constexpr int NG  = NF / 2;
    constexpr int LDS = BK + 8;            // halfs per smem row
    constexpr int ATA = BM * LDS;
    constexpr int ATB = BN * LDS;
    constexpr int STG = ATA + ATB;
    constexpr int CHA = BK / 8;            // 16B chunks per row
    extern __shared__ __half sm[];

    const int tid  = threadIdx.x;
    const int lane = tid & 31, wid = tid >> 5;
    const int wm = wid / WNW, wn = wid % WNW;
    const int bm = blockIdx.y * BM, bn = blockIdx.x * BN;
    const int KIT = K / BK;
    const int ITERS = KIT + (LORA ? (ER / BK) : 0);

    float acc[MF][NF][4];
    #pragma unroll
    for (int i = 0; i < MF; i++)
        #pragma unroll
        for (int j = 0; j < NF; j++)
            #pragma unroll
            for (int v = 0; v < 4; v++) acc[i][j][v] = 0.f;

    auto load_stage = [&](int it) {
        __half* dA = sm + (it % 3) * STG;
        __half* dB = dA + ATA;
        const __half *sa, *sb;
        int ld, k0;
        if (!LORA || it < KIT) { sa = A;  sb = B;  ld = K;  k0 = it * BK; }
        else                   { sa = gA; sb = gB; ld = ER; k0 = (it - KIT) * BK; }
        #pragma unroll
        for (int i = 0; i < (BM * CHA) / THREADS; i++) {
            int c = tid + i * THREADS, row = c / CHA, ch = c % CHA;
            cp16(cvta_s(dA + row * LDS + ch * 8),
                 sa + (size_t)(bm + row) * ld + k0 + ch * 8);
        }
        #pragma unroll
        for (int i = 0; i < (BN * CHA) / THREADS; i++) {
            int c = tid + i * THREADS, row = c / CHA, ch = c % CHA;
            cp16(cvta_s(dB + row * LDS + ch * 8),
                 sb + (size_t)(bn + row) * ld + k0 + ch * 8);
        }
    };

    // prologue: 2 stages in flight
    for (int it = 0; it < 2; ++it) { load_stage(it); CP_COMMIT(); }

    for (int it = 0; it < ITERS; ++it) {
        CP_WAIT1();                 // group `it` complete (1 newer pending)
        __syncthreads();            // all warps done with slot (it+2)%3==(it-1)%3
        if (it + 2 < ITERS) load_stage(it + 2);
        CP_COMMIT();                // keep group count in step

        const uint32_t sa = cvta_s(sm + (it % 3) * STG);
        const uint32_t sb = sa + ATA * 2;
        #pragma unroll
        for (int kp = 0; kp < BK / 16; kp++) {
            uint32_t a[MF][4], b[NG][4];
            #pragma unroll
            for (int mf = 0; mf < MF; mf++) {
                int r  = wm * MF * 16 + mf * 16 + (lane & 7) + ((lane >> 3) & 1) * 8;
                int cl = kp * 16 + ((lane >> 4) & 1) * 8;
                ldsm4(a[mf][0], a[mf][1], a[mf][2], a[mf][3],
                      sa + (r * LDS + cl) * 2);
            }
            #pragma unroll
            for (int g = 0; g < NG; g++) {
                int nr = wn * WN + g * 16 + ((lane >> 4) & 1) * 8 + (lane & 7);
                int cl = kp * 16 + ((lane >> 3) & 1) * 8;
                ldsm4(b[g][0], b[g][1], b[g][2], b[g][3],
                      sb + (nr * LDS + cl) * 2);
            }
            #pragma unroll
            for (int mf = 0; mf < MF; mf++)
                #pragma unroll
                for (int nf = 0; nf < NF; nf++)
                    mma16816(acc[mf][nf], a[mf],
                             b[nf >> 1][(nf & 1) * 2], b[nf >> 1][(nf & 1) * 2 + 1]);
        }
    }

    #pragma unroll
    for (int mf = 0; mf < MF; mf++) {
        #pragma unroll
        for (int nf = 0; nf < NF; nf++) {
            int row = bm + wm * MF * 16 + mf * 16 + (lane >> 2);
            int col = bn + wn * WN + nf * 8 + (lane & 3) * 2;
            float b0 = 0.f, b1 = 0.f;
            if (bias) { b0 = bias[col]; b1 = bias[col + 1]; }
            float2 v0 = {acc[mf][nf][0] + b0, acc[mf][nf][1] + b1};
            float2 v1 = {acc[mf][nf][2] + b0, acc[mf][nf][3] + b1};
            *(float2*)(C + (size_t)row * ldc + col)       = v0;
            *(float2*)(C + (size_t)(row + 8) * ldc + col) = v1;
        }
    }
}

// main: 2x8 warps (512 thr), 64x32 warp tile, 128x256 CTA, BK=64, 1 CTA/SM
using GemmMain = void(const __half*, const __half*, const __half*,
                      const __half*, const float*, float*, int, int);
constexpr int SMEM_MAIN = 3 * (128 + 256) * (64 + 8) * 2;   // 165888
// proj: 1x4 warps (128 thr), 64x32 warp tile, 64x128 CTA, BK=64, 2 CTA/SM
constexpr int SMEM_PROJ = 3 * (64 + 128) * (64 + 8) * 2;    //  82944

// ---------------------------------------------------------------------------
// Merged fp32->fp16 conversion for x, W, Wq, Wk, A in ONE launch.
// ---------------------------------------------------------------------------
#define CONV_THREADS 256
#define CONV_UNROLL  4
#define CHUNK (CONV_THREADS * CONV_UNROLL)   // 1024 float4 per block

__global__ __launch_bounds__(CONV_THREADS)
void k_convert(const float4* __restrict__ x,  const float4* __restrict__ W,
               const float4* __restrict__ Wq, const float4* __restrict__ Wk,
               const float4* __restrict__ A)
{
    constexpr int NB_X  = (M_TOK * DIN / 4) / CHUNK;
    constexpr int NB_W  = (DOUT  * DIN / 4) / CHUNK;
    constexpr int NB_Q  = (EQ    * DIN / 4) / CHUNK;
    constexpr int NB_K  = (EQ    * DIN / 4) / CHUNK;

    int bidx = blockIdx.x;
    const float4* src;
    __half2* dst;
    if (bidx < NB_X) {
        src = x;  dst = (__half2*)g_xh;
    } else if ((bidx -= NB_X) < NB_W) {
        src = W;  dst = (__half2*)g_Wh;
    } else if ((bidx -= NB_W) < NB_Q) {
        src = Wq; dst = (__half2*)g_Wp;
    } else if ((bidx -= NB_Q) < NB_K) {
        src = Wk; dst = (__half2*)(g_Wp + (size_t)EQ * DIN);
    } else {
        bidx -= NB_K;
        src = A;  dst = (__half2*)(g_Wp + (size_t)2 * EQ * DIN);
    }
    int base = bidx * CHUNK + threadIdx.x;
    float4 v[CONV_UNROLL];
    #pragma unroll
    for (int u = 0; u < CONV_UNROLL; u++) v[u] = src[base + u * CONV_THREADS];
    #pragma unroll
    for (int u = 0; u < CONV_UNROLL; u++) {
        int i = base + u * CONV_THREADS;
        dst[2 * i + 0] = __halves2half2(__float2half_rn(v[u].x), __float2half_rn(v[u].y));
        dst[2 * i + 1] = __halves2half2(__float2half_rn(v[u].z), __float2half_rn(v[u].w));
    }
}
#define CONV_BLOCKS ((M_TOK*DIN/4 + DOUT*DIN/4 + 2*(EQ*DIN/4) + ER*DIN/4) / CHUNK)

__global__ void k_bmt(const float* __restrict__ Bm) {
    int idx = blockIdx.x * blockDim.x + threadIdx.x;
    if (idx >= DOUT * ER) return;
    int o = idx >> 7, j = idx & 127;
    int e = j >> 4, r = j & 15;
    g_Bmt[idx] = __float2half_rn(Bm[((size_t)e * DOUT + o) * RK + r]);
}

// softmax over experts + gate
__global__ __launch_bounds__(256) void k_gate() {
    int t = (blockIdx.x * 256 + threadIdx.x) >> 5;
    int lane = threadIdx.x & 31;
    if (t >= M_TOK) return;
    const float* p = g_proj + (size_t)t * NPROJ;
    float s[NE];
    #pragma unroll
    for (int e = 0; e < NE; e++) {
        float v = p[e * 32 + lane] * p[EQ + e * 32 + lane];
        #pragma unroll
        for (int o = 16; o > 0; o >>= 1) v += __shfl_xor_sync(0xffffffffu, v, o);
        s[e] = v * INV_SQRT_DK;
    }
    float m = s[0];
    #pragma unroll
    for (int e = 1; e < NE; e++) m = fmaxf(m, s[e]);
    float sum = 0.f;
    #pragma unroll
    for (int e = 0; e < NE; e++) { s[e] = expf(s[e] - m); sum += s[e]; }
    float inv = 1.f / sum;
    #pragma unroll
    for (int j = 0; j < 4; j++) {
        int er = lane * 4 + j;
        int e = er >> 4;
        g_gate[(size_t)t * ER + er] = __float2half_rn(s[e] * inv * p[2 * EQ + er]);
    }
}

// ---------------------------------------------------------------------------
extern "C" void kernel_launch(void* const* d_in, const int* in_sizes, int n_in,
                              void* d_out, int out_size) {
    const float* x  = (const float*)d_in[0];
    const float* W  = (const float*)d_in[1];
    const float* b  = (const float*)d_in[2];
    const float* Wq = (const float*)d_in[3];
    const float* Wk = (const float*)d_in[4];
    const float* A  = (const float*)d_in[5];
    const float* Bm = (const float*)d_in[6];
    float* out = (float*)d_out;

    __half *xh, *Wh, *Wp, *Bmt, *gate; float* proj;
    cudaGetSymbolAddress((void**)&xh,   g_xh);
    cudaGetSymbolAddress((void**)&Wh,   g_Wh);
    cudaGetSymbolAddress((void**)&Wp,   g_Wp);
    cudaGetSymbolAddress((void**)&Bmt,  g_Bmt);
    cudaGetSymbolAddress((void**)&gate, g_gate);
    cudaGetSymbolAddress((void**)&proj, g_proj);

    cudaFuncSetAttribute((GemmMain*)gemm_hmma<2, 8, 4, 4, 64, 1, true>,
                         cudaFuncAttributeMaxDynamicSharedMemorySize, SMEM_MAIN);
    cudaFuncSetAttribute((GemmMain*)gemm_hmma<1, 4, 4, 4, 64, 2, false>,
                         cudaFuncAttributeMaxDynamicSharedMemorySize, SMEM_PROJ);

    // [0] merged fp32->fp16 conversions (x, W, Wq, Wk, A)
    k_convert<<<CONV_BLOCKS, CONV_THREADS>>>((const float4*)x, (const float4*)W,
                                             (const float4*)Wq, (const float4*)Wk,
                                             (const float4*)A);
    // [1] Bm transpose/convert
    k_bmt<<<(DOUT * ER + 255) / 256, 256>>>(Bm);

    // [2] projections: proj[8192, 640] = xh @ Wp^T   (64x128 tiles, 640 CTAs)
    gemm_hmma<1, 4, 4, 4, 64, 2, false><<<dim3(NPROJ / 128, M_TOK / 64), 128, SMEM_PROJ>>>(
        xh, Wp, nullptr, nullptr, nullptr, proj, NPROJ, DIN);

    // [3] softmax + gating
    k_gate<<<M_TOK / 8, 256>>>();

    // [4] fused: out = xh@Wh^T + gate@Bmt^T + bias   (128x256 tiles, 512 thr)
    gemm_hmma<2, 8, 4, 4, 64, 1, true><<<dim3(DOUT / 256, M_TOK / 128), 512, SMEM_MAIN>>>(
        xh, Wh, gate, Bmt, b, out, DOUT, DIN);
}

// round 10
// speedup vs baseline: 1.0347x; 1.0347x over previous
#include <cuda_runtime.h>
#include <cuda_fp16.h>
#include <cstdint>

#define M_TOK 8192
#define DIN   4096
#define DOUT  4096
#define NE    8
#define RK    16
#define EQ    256
#define ER    128
#define NPROJ 640           // EQ + EQ + ER
#define INV_SQRT_DK 0.17677669529663687f

// ---------------- scratch (no allocs allowed) ----------------
__device__ __half g_xh [(size_t)M_TOK * DIN];
__device__ __half g_Wh [(size_t)DOUT  * DIN];
__device__ __half g_Wp [(size_t)NPROJ * DIN];
__device__ __half g_Bmt[(size_t)DOUT  * ER];
__device__ float  g_proj[(size_t)M_TOK * NPROJ];
__device__ __half g_gate[(size_t)M_TOK * ER];

// ---------------- PTX helpers (base-target only) ----------
__device__ __forceinline__ uint32_t cvta_s(const void* p) {
    return (uint32_t)__cvta_generic_to_shared(p);
}
__device__ __forceinline__ void cp16(uint32_t dst, const void* src) {
    asm volatile("cp.async.cg.shared.global [%0], [%1], 16;" :: "r"(dst), "l"(src));
}
#define CP_COMMIT() asm volatile("cp.async.commit_group;" ::: "memory")
#define CP_WAIT1()  asm volatile("cp.async.wait_group 1;"  ::: "memory")

__device__ __forceinline__ void ldsm4(uint32_t& r0, uint32_t& r1,
                                      uint32_t& r2, uint32_t& r3, uint32_t addr) {
    asm volatile("ldmatrix.sync.aligned.m8n8.x4.shared.b16 {%0,%1,%2,%3}, [%4];"
                 : "=r"(r0), "=r"(r1), "=r"(r2), "=r"(r3) : "r"(addr));
}
__device__ __forceinline__ void mma16816(float* d, const uint32_t* a,
                                         uint32_t b0, uint32_t b1) {
    asm volatile(
        "mma.sync.aligned.m16n8k16.row.col.f32.f16.f16.f32 "
        "{%0,%1,%2,%3}, {%4,%5,%6,%7}, {%8,%9}, {%0,%1,%2,%3};"
        : "+f"(d[0]), "+f"(d[1]), "+f"(d[2]), "+f"(d[3])
        : "r"(a[0]), "r"(a[1]), "r"(a[2]), "r"(a[3]), "r"(b0), "r"(b1));
}

// ---------------------------------------------------------------------------
// Generalized HMMA fp16 GEMM (R7-proven order: wait -> sync -> load -> compute).
//   Warp grid WMW x WNW; warp tile (MF*16) x (NF*8); CTA tile BM x BN.
//   BK K-slice per stage; 3-slot, depth-2 cp.async pipeline.
//   C = A @ B^T (+ gA @ gB^T over K=ER if LORA) (+ bias).
//   A[M,K], B[N,K] row-major fp16, K contiguous.
//   Smem rows padded to BK+8 halfs -> ldmatrix conflict-free.
// ---------------------------------------------------------------------------
template<int WMW, int WNW, int MF, int NF, int BK, int MINB, bool LORA>
__global__ __launch_bounds__(WMW * WNW * 32, MINB)
void gemm_hmma(const __half* __restrict__ A, const __half* __restrict__ B,
               const __half* __restrict__ gA, const __half* __restrict__ gB,
               const float* __restrict__ bias,
               float* __restrict__ C, int ldc, int K)
{
    constexpr int THREADS = WMW * WNW * 32;
    constexpr int BM  = WMW * MF * 16;
    constexpr int BN  = WNW * NF * 8;
    constexpr int WN  = NF * 8;
    constexpr int NG  = NF / 2;
    constexpr int LDS = BK + 8;            // halfs per smem row
    constexpr int ATA = BM * LDS;
    constexpr int ATB = BN * LDS;
    constexpr int STG = ATA + ATB;
    constexpr int CHA = BK / 8;            // 16B chunks per row
    extern __shared__ __half sm[];

    const int tid  = threadIdx.x;
    const int lane = tid & 31, wid = tid >> 5;
    const int wm = wid / WNW, wn = wid % WNW;
    const int bm = blockIdx.y * BM, bn = blockIdx.x * BN;
    const int KIT = K / BK;
    const int ITERS = KIT + (LORA ? (ER / BK) : 0);

    float acc[MF][NF][4];
    #pragma unroll
    for (int i = 0; i < MF; i++)
        #pragma unroll
        for (int j = 0; j < NF; j++)
            #pragma unroll
            for (int v = 0; v < 4; v++) acc[i][j][v] = 0.f;

    auto load_stage = [&](int it) {
        __half* dA = sm + (it % 3) * STG;
        __half* dB = dA + ATA;
        const __half *sa, *sb;
        int ld, k0;
        if (!LORA || it < KIT) { sa = A;  sb = B;  ld = K;  k0 = it * BK; }
        else                   { sa = gA; sb = gB; ld = ER; k0 = (it - KIT) * BK; }
        #pragma unroll
        for (int i = 0; i < (BM * CHA) / THREADS; i++) {
            int c = tid + i * THREADS, row = c / CHA, ch = c % CHA;
            cp16(cvta_s(dA + row * LDS + ch * 8),
                 sa + (size_t)(bm + row) * ld + k0 + ch * 8);
        }
        #pragma unroll
        for (int i = 0; i < (BN * CHA) / THREADS; i++) {
            int c = tid + i * THREADS, row = c / CHA, ch = c % CHA;
            cp16(cvta_s(dB + row * LDS + ch * 8),
                 sb + (size_t)(bn + row) * ld + k0 + ch * 8);
        }
    };

    // prologue: 2 stages in flight
    for (int it = 0; it < 2; ++it) { load_stage(it); CP_COMMIT(); }

    for (int it = 0; it < ITERS; ++it) {
        CP_WAIT1();                 // own group `it` drained (1 newer pending)
        __syncthreads();            // CTA-wide: group `it` visible; slot (it-1)%3 free
        if (it + 2 < ITERS) load_stage(it + 2);
        CP_COMMIT();                // keep group count in step

        const uint32_t sa = cvta_s(sm + (it % 3) * STG);
        const uint32_t sb = sa + ATA * 2;
        #pragma unroll
        for (int kp = 0; kp < BK / 16; kp++) {
            uint32_t a[MF][4], b[NG][4];
            #pragma unroll
            for (int mf = 0; mf < MF; mf++) {
                int r  = wm * MF * 16 + mf * 16 + (lane & 7) + ((lane >> 3) & 1) * 8;
                int cl = kp * 16 + ((lane >> 4) & 1) * 8;
                ldsm4(a[mf][0], a[mf][1], a[mf][2], a[mf][3],
                      sa + (r * LDS + cl) * 2);
            }
            #pragma unroll
            for (int g = 0; g < NG; g++) {
                int nr = wn * WN + g * 16 + ((lane >> 4) & 1) * 8 + (lane & 7);
                int cl = kp * 16 + ((lane >> 3) & 1) * 8;
                ldsm4(b[g][0], b[g][1], b[g][2], b[g][3],
                      sb + (nr * LDS + cl) * 2);
            }
            #pragma unroll
            for (int mf = 0; mf < MF; mf++)
                #pragma unroll
                for (int nf = 0; nf < NF; nf++)
                    mma16816(acc[mf][nf], a[mf],
                             b[nf >> 1][(nf & 1) * 2], b[nf >> 1][(nf & 1) * 2 + 1]);
        }
    }

    #pragma unroll
    for (int mf = 0; mf < MF; mf++) {
        #pragma unroll
        for (int nf = 0; nf < NF; nf++) {
            int row = bm + wm * MF * 16 + mf * 16 + (lane >> 2);
            int col = bn + wn * WN + nf * 8 + (lane & 3) * 2;
            float b0 = 0.f, b1 = 0.f;
            if (bias) { b0 = bias[col]; b1 = bias[col + 1]; }
            float2 v0 = {acc[mf][nf][0] + b0, acc[mf][nf][1] + b1};
            float2 v1 = {acc[mf][nf][2] + b0, acc[mf][nf][3] + b1};
            *(float2*)(C + (size_t)row * ldc + col)       = v0;
            *(float2*)(C + (size_t)(row + 8) * ldc + col) = v1;
        }
    }
}

// main: 2x4 warps, 64x32 warp tile, 128x128 CTA, BK=64, 2 CTA/SM  (R7 config)
using GemmMain = void(const __half*, const __half*, const __half*,
                      const __half*, const float*, float*, int, int);
constexpr int SMEM_MAIN = 3 * (128 + 128) * (64 + 8) * 2;   // 110592
// proj: 1x4 warps, 64x32 warp tile, 64x128 CTA, BK=64, 2 CTA/SM
constexpr int SMEM_PROJ = 3 * (64 + 128) * (64 + 8) * 2;    //  82944

// ---------------------------------------------------------------------------
// Merged conversion: fp32->fp16 for x, W, Wq, Wk, A  PLUS the Bm transpose
// (Bmt[o, e*16+r] = half(Bm[e, o, r])) in ONE launch.
// ---------------------------------------------------------------------------
#define CONV_THREADS 256
#define CONV_UNROLL  4
#define CHUNK (CONV_THREADS * CONV_UNROLL)   // 1024 float4 per block

__global__ __launch_bounds__(CONV_THREADS)
void k_convert(const float4* __restrict__ x,  const float4* __restrict__ W,
               const float4* __restrict__ Wq, const float4* __restrict__ Wk,
               const float4* __restrict__ A,  const float* __restrict__ Bm)
{
    constexpr int NB_X  = (M_TOK * DIN / 4) / CHUNK;   // 8192
    constexpr int NB_W  = (DOUT  * DIN / 4) / CHUNK;   // 4096
    constexpr int NB_Q  = (EQ    * DIN / 4) / CHUNK;   // 256
    constexpr int NB_K  = (EQ    * DIN / 4) / CHUNK;   // 256
    constexpr int NB_A  = (ER    * DIN / 4) / CHUNK;   // 128

    int bidx = blockIdx.x;
    const float4* src;
    __half2* dst;
    if (bidx < NB_X) {
        src = x;  dst = (__half2*)g_xh;
    } else if ((bidx -= NB_X) < NB_W) {
        src = W;  dst = (__half2*)g_Wh;
    } else if ((bidx -= NB_W) < NB_Q) {
        src = Wq; dst = (__half2*)g_Wp;
    } else if ((bidx -= NB_Q) < NB_K) {
        src = Wk; dst = (__half2*)(g_Wp + (size_t)EQ * DIN);
    } else if ((bidx -= NB_K) < NB_A) {
        src = A;  dst = (__half2*)(g_Wp + (size_t)2 * EQ * DIN);
    } else {
        // Bm transpose blocks: 256 blocks x 256 threads x 8 elems
        bidx -= NB_A;
        int base = bidx * (CONV_THREADS * 8) + threadIdx.x * 8;  // mult of 8
        int o = base >> 7, j = base & 127;        // j multiple of 8
        int e = j >> 4, r = j & 15;               // r in {0,8}, e fixed for 8 elems
        const float* s = Bm + ((size_t)e * DOUT + o) * RK + r;
        float4 v0 = *(const float4*)s, v1 = *(const float4*)(s + 4);
        __half2 h[4];
        h[0] = __halves2half2(__float2half_rn(v0.x), __float2half_rn(v0.y));
        h[1] = __halves2half2(__float2half_rn(v0.z), __float2half_rn(v0.w));
        h[2] = __halves2half2(__float2half_rn(v1.x), __float2half_rn(v1.y));
        h[3] = __halves2half2(__float2half_rn(v1.z), __float2half_rn(v1.w));
        *(uint4*)(g_Bmt + base) = *(uint4*)h;
        return;
    }
    int base = bidx * CHUNK + threadIdx.x;
    float4 v[CONV_UNROLL];
    #pragma unroll
    for (int u = 0; u < CONV_UNROLL; u++) v[u] = src[base + u * CONV_THREADS];
    #pragma unroll
    for (int u = 0; u < CONV_UNROLL; u++) {
        int i = base + u * CONV_THREADS;
        dst[2 * i + 0] = __halves2half2(__float2half_rn(v[u].x), __float2half_rn(v[u].y));
        dst[2 * i + 1] = __halves2half2(__float2half_rn(v[u].z), __float2half_rn(v[u].w));
    }
}
#define NB_BMT ((DOUT * ER) / (CONV_THREADS * 8))    // 256
#define CONV_BLOCKS ((M_TOK*DIN/4 + DOUT*DIN/4 + 2*(EQ*DIN/4) + ER*DIN/4) / CHUNK + NB_BMT)

// softmax over experts + gate
__global__ __launch_bounds__(256) void k_gate() {
    int t = (blockIdx.x * 256 + threadIdx.x) >> 5;
    int lane = threadIdx.x & 31;
    if (t >= M_TOK) return;
    const float* p = g_proj + (size_t)t * NPROJ;
    float s[NE];
    #pragma unroll
    for (int e = 0; e < NE; e++) {
        float v = p[e * 32 + lane] * p[EQ + e * 32 + lane];
        #pragma unroll
        for (int o = 16; o > 0; o >>= 1) v += __shfl_xor_sync(0xffffffffu, v, o);
        s[e] = v * INV_SQRT_DK;
    }
    float m = s[0];
    #pragma unroll
    for (int e = 1; e < NE; e++) m = fmaxf(m, s[e]);
    float sum = 0.f;
    #pragma unroll
    for (int e = 0; e < NE; e++) { s[e] = expf(s[e] - m); sum += s[e]; }
    float inv = 1.f / sum;
    #pragma unroll
    for (int j = 0; j < 4; j++) {
        int er = lane * 4 + j;
        int e = er >> 4;
        g_gate[(size_t)t * ER + er] = __float2half_rn(s[e] * inv * p[2 * EQ + er]);
    }
}

// ---------------------------------------------------------------------------
extern "C" void kernel_launch(void* const* d_in, const int* in_sizes, int n_in,
                              void* d_out, int out_size) {
    const float* x  = (const float*)d_in[0];
    const float* W  = (const float*)d_in[1];
    const float* b  = (const float*)d_in[2];
    const float* Wq = (const float*)d_in[3];
    const float* Wk = (const float*)d_in[4];
    const float* A  = (const float*)d_in[5];
    const float* Bm = (const float*)d_in[6];
    float* out = (float*)d_out;

    __half *xh, *Wh, *Wp, *Bmt, *gate; float* proj;
    cudaGetSymbolAddress((void**)&xh,   g_xh);
    cudaGetSymbolAddress((void**)&Wh,   g_Wh);
    cudaGetSymbolAddress((void**)&Wp,   g_Wp);
    cudaGetSymbolAddress((void**)&Bmt,  g_Bmt);
    cudaGetSymbolAddress((void**)&gate, g_gate);
    cudaGetSymbolAddress((void**)&proj, g_proj);

    cudaFuncSetAttribute((GemmMain*)gemm_hmma<2, 4, 4, 4, 64, 2, true>,
                         cudaFuncAttributeMaxDynamicSharedMemorySize, SMEM_MAIN);
    cudaFuncSetAttribute((GemmMain*)gemm_hmma<1, 4, 4, 4, 64, 2, false>,
                         cudaFuncAttributeMaxDynamicSharedMemorySize, SMEM_PROJ);

    // [0] merged conversions (x, W, Wq, Wk, A) + Bm transpose
    k_convert<<<CONV_BLOCKS, CONV_THREADS>>>((const float4*)x, (const float4*)W,
                                             (const float4*)Wq, (const float4*)Wk,
                                             (const float4*)A, Bm);

    // [1] projections: proj[8192, 640] = xh @ Wp^T   (64x128 tiles, 640 CTAs)
    gemm_hmma<1, 4, 4, 4, 64, 2, false><<<dim3(NPROJ / 128, M_TOK / 64), 128, SMEM_PROJ>>>(
        xh, Wp, nullptr, nullptr, nullptr, proj, NPROJ, DIN);

    // [2] softmax + gating
    k_gate<<<M_TOK / 8, 256>>>();

    // [3] fused: out = xh@Wh^T + gate@Bmt^T + bias   (128x128 tiles, BK=64)
    gemm_hmma<2, 4, 4, 4, 64, 2, true><<<dim3(DOUT / 128, M_TOK / 128), 256, SMEM_MAIN>>>(
        xh, Wh, gate, Bmt, b, out, DOUT, DIN);
}